// round 1
// baseline (speedup 1.0000x reference)
#include <cuda_runtime.h>
#include <cuda_bf16.h>

#define Kdim 256
#define Ndim 65536
#define TT   128                 // time-tile width
#define NTILES (Ndim / TT)       // 512
#define KPAD 264                 // K + 8 pad -> conflict-free fragment LDS
#define CH   128                 // scan chunk per thread
#define LB   64                  // scan warmup lookback (e^-64 ~ 1e-28)

// ---------------- scratch (static device globals; no allocation) -------------
__device__ __nv_bfloat16 g_S[(size_t)Kdim * Ndim];   // S[k][n] = Beta*H(n-1), n>=1; S[:,0]=0
__device__ float  g_Mu0[Kdim];
__device__ double g_ll;

// ---------------- zero the loglik accumulator --------------------------------
__global__ void k_zero() { g_ll = 0.0; }

// ---------------- Mu0 = mean(obs, axis=1)/10 + 0.01  (deterministic) ---------
__global__ void k_rowmean(const float* __restrict__ obs) {
    int k = blockIdx.x;
    const float4* p = (const float4*)(obs + (size_t)k * Ndim);
    float ax = 0.f, ay = 0.f, az = 0.f, aw = 0.f;
    for (int i = threadIdx.x; i < Ndim / 4; i += 256) {
        float4 v = p[i];
        ax += v.x; ay += v.y; az += v.z; aw += v.w;
    }
    float s = (ax + ay) + (az + aw);
    __shared__ float red[256];
    red[threadIdx.x] = s;
    __syncthreads();
    for (int o = 128; o > 0; o >>= 1) {
        if (threadIdx.x < o) red[threadIdx.x] += red[threadIdx.x + o];
        __syncthreads();
    }
    if (threadIdx.x == 0) g_Mu0[k] = red[0] * (1.0f / Ndim) * 0.1f + 0.01f;
}

// ---------------- S kernel: truncated exponential-kernel scan ----------------
// S[k][n] = Beta[k] * H(n-1), H(i) = decay*(H(i-1) + obs[k][i]).
// decay <= e^-1, so a 64-step warmup reproduces H to ~1e-28.
__global__ void k_S(const float* __restrict__ obs, const float* __restrict__ Beta) {
    int u  = blockIdx.x * blockDim.x + threadIdx.x;  // 256*512 threads
    int k  = u >> 9;                                  // row
    int c  = u & 511;                                 // chunk
    int n0 = c * CH;

    float beta  = Beta[k];
    float decay = expf(-beta);
    const float* orow = obs + (size_t)k * Ndim;

    float h = 0.f;
    int is = n0 - 1 - LB;
    if (is < 0) is = 0;
    for (int i = is; i < n0 - 1; ++i)
        h = decay * (h + __ldg(orow + i));

    union { __nv_bfloat16 b[8]; uint4 v; } buf;
    uint4* outp = (uint4*)(g_S + (size_t)k * Ndim + n0);
    int n = n0;
    for (int q = 0; q < CH / 8; ++q) {
        #pragma unroll
        for (int r = 0; r < 8; ++r) {
            float val = 0.f;
            if (n > 0) {
                h = decay * (h + __ldg(orow + n - 1));
                val = beta * h;
            }
            buf.b[r] = __float2bfloat16(val);
            ++n;
        }
        outp[q] = buf.v;
    }
}

// ---------------- bf16 mma helper --------------------------------------------
__device__ __forceinline__ void mma16816(float* c, const unsigned* a, unsigned b0, unsigned b1) {
    asm volatile(
        "mma.sync.aligned.m16n8k16.row.col.f32.bf16.bf16.f32 "
        "{%0,%1,%2,%3}, {%4,%5,%6,%7}, {%8,%9}, {%0,%1,%2,%3};\n"
        : "+f"(c[0]), "+f"(c[1]), "+f"(c[2]), "+f"(c[3])
        : "r"(a[0]), "r"(a[1]), "r"(a[2]), "r"(a[3]), "r"(b0), "r"(b1));
}

// ---------------- fused GEMM (lam1 = softplus(Alpha @ S)) + epilogue ---------
// Persistent CTAs: Alpha (256x256 bf16) staged in smem ONCE per CTA; each loop
// iteration stages one S time-tile [TT x K] transposed to [t][k] and runs the
// full K=256 reduction from smem (no k-staging loop needed).
__global__ __launch_bounds__(256, 1) void k_gemm(
    const float* __restrict__ obs,
    const float* __restrict__ Alpha,
    float* __restrict__ out)
{
    extern __shared__ __align__(16) char smem[];
    __nv_bfloat16* As   = (__nv_bfloat16*)smem;        // [256][KPAD]
    __nv_bfloat16* Ss   = As + 256 * KPAD;             // [TT][KPAD]
    float*         Mu0s = (float*)(Ss + TT * KPAD);    // [256]
    double*        red  = (double*)(Mu0s + 256);       // [8]

    const int tid  = threadIdx.x;
    const int wid  = tid >> 5, lane = tid & 31;
    const int wj   = wid & 3;          // 4 warps along j (64 rows each)
    const int wt   = wid >> 2;         // 2 warps along t (64 cols each)
    const int lg   = lane >> 2;        // group id (row within fragment)
    const int lm   = lane & 3;         // thread-in-group

    // Stage Alpha -> bf16 smem (row-major [j][k])
    const float4* A4 = (const float4*)Alpha;
    for (int idx = tid; idx < Kdim * Kdim / 4; idx += 256) {
        int j = idx >> 6, c4 = idx & 63;
        float4 v = A4[idx];
        __nv_bfloat162* dst = (__nv_bfloat162*)(As + j * KPAD + c4 * 4);
        dst[0] = __floats2bfloat162_rn(v.x, v.y);
        dst[1] = __floats2bfloat162_rn(v.z, v.w);
    }
    Mu0s[tid] = g_Mu0[tid];

    float* lams0 = out + 1;
    float* lams1 = out + 1 + (size_t)Kdim * Ndim;

    double lsum = 0.0;

    for (int tile = blockIdx.x; tile < NTILES; tile += gridDim.x) {
        const int n0 = tile * TT;
        __syncthreads();   // WAR on Ss vs previous iteration (and Alpha staging on iter 0)

        // Stage S tile transposed: Ss[t][k], thread = k-row, 16B global loads
        {
            const uint4* srow = (const uint4*)(g_S + (size_t)tid * Ndim + n0);
            #pragma unroll
            for (int q = 0; q < TT / 8; ++q) {
                uint4 v = srow[q];
                const __nv_bfloat16* bb = (const __nv_bfloat16*)&v;
                #pragma unroll
                for (int r = 0; r < 8; ++r)
                    Ss[(q * 8 + r) * KPAD + tid] = bb[r];
            }
        }
        __syncthreads();

        float acc[4][8][4];
        #pragma unroll
        for (int a = 0; a < 4; ++a)
            #pragma unroll
            for (int b = 0; b < 8; ++b)
                #pragma unroll
                for (int d = 0; d < 4; ++d) acc[a][b][d] = 0.f;

        #pragma unroll
        for (int ks = 0; ks < Kdim / 16; ++ks) {
            const int kk = ks * 16;
            unsigned afrag[4][4];
            #pragma unroll
            for (int mf = 0; mf < 4; ++mf) {
                int j = wj * 64 + mf * 16 + lg;
                const unsigned* r0 = (const unsigned*)(As + j * KPAD + kk) + lm;
                const unsigned* r1 = (const unsigned*)(As + (j + 8) * KPAD + kk) + lm;
                afrag[mf][0] = r0[0];
                afrag[mf][1] = r1[0];
                afrag[mf][2] = r0[4];
                afrag[mf][3] = r1[4];
            }
            #pragma unroll
            for (int nf = 0; nf < 8; ++nf) {
                int t = wt * 64 + nf * 8 + lg;
                const unsigned* rb = (const unsigned*)(Ss + t * KPAD + kk) + lm;
                unsigned b0 = rb[0], b1 = rb[4];
                #pragma unroll
                for (int mf = 0; mf < 4; ++mf)
                    mma16816(acc[mf][nf], afrag[mf], b0, b1);
            }
        }

        // Epilogue: softplus, lams writes, loglik terms
        #pragma unroll
        for (int mf = 0; mf < 4; ++mf) {
            #pragma unroll
            for (int nf = 0; nf < 8; ++nf) {
                const int tloc = wt * 64 + nf * 8 + lm * 2;
                const int n    = n0 + tloc;
                #pragma unroll
                for (int half = 0; half < 2; ++half) {
                    const int jj = wj * 64 + mf * 16 + lg + half * 8;
                    float z0 = acc[mf][nf][half * 2 + 0];
                    float z1 = acc[mf][nf][half * 2 + 1];
                    // softplus(z) = z + log(1 + e^-z); z >= 0 here
                    float lam0 = z0 + __logf(1.f + __expf(-z0));
                    float lam1v = z1 + __logf(1.f + __expf(-z1));
                    if (n == 0) lam0 = 0.f;   // reference forces lams1[:,0] = 0
                    const float mu = Mu0s[jj];
                    const size_t base = (size_t)jj * Ndim + n;
                    // d_out+1 base is 4B-aligned only -> scalar stores
                    lams1[base]     = lam0;
                    lams1[base + 1] = lam1v;
                    lams0[base]     = mu;
                    lams0[base + 1] = mu;
                    float2 ov = *(const float2*)(obs + base);  // obs itself is 8B aligned
                    float t0 = ov.x * __logf(mu + lam0 + 1e-5f) - mu - lam0;
                    float t1 = ov.y * __logf(mu + lam1v + 1e-5f) - mu - lam1v;
                    lsum += (double)(t0 + t1);
                }
            }
        }
    }

    // Reduce loglik: warp shuffle -> smem -> one atomicAdd(double) per CTA
    #pragma unroll
    for (int o = 16; o > 0; o >>= 1)
        lsum += __shfl_down_sync(0xffffffffu, lsum, o);
    if (lane == 0) red[wid] = lsum;
    __syncthreads();
    if (tid == 0) {
        double s = 0.0;
        #pragma unroll
        for (int i = 0; i < 8; ++i) s += red[i];
        atomicAdd(&g_ll, s);
    }
}

__global__ void k_final(float* __restrict__ out) { out[0] = (float)g_ll; }

// ---------------- launch ------------------------------------------------------
extern "C" void kernel_launch(void* const* d_in, const int* in_sizes, int n_in,
                              void* d_out, int out_size) {
    const float* obs   = (const float*)d_in[0];
    const float* Beta  = (const float*)d_in[1];
    const float* Alpha = (const float*)d_in[2];
    float* out = (float*)d_out;

    k_zero<<<1, 1>>>();
    k_rowmean<<<Kdim, 256>>>(obs);
    k_S<<<(Kdim * (Ndim / CH)) / 256, 256>>>(obs, Beta);

    const int smem_bytes = 256 * KPAD * 2 + TT * KPAD * 2 + 256 * 4 + 8 * 8;
    cudaFuncSetAttribute(k_gemm, cudaFuncAttributeMaxDynamicSharedMemorySize, smem_bytes);
    int nsm = 148;
    cudaDeviceGetAttribute(&nsm, cudaDevAttrMultiProcessorCount, 0);
    k_gemm<<<nsm, 256, smem_bytes>>>(obs, Alpha, out);

    k_final<<<1, 1>>>(out);
}

// round 2
// speedup vs baseline: 2.2818x; 2.2818x over previous
#include <cuda_runtime.h>
#include <cuda_bf16.h>

#define Kdim 256
#define Ndim 65536
#define TT   128                 // time-tile width
#define NTILES (Ndim / TT)       // 512
#define KPAD 264                 // K + 8 pad -> conflict-free fragment LDS
#define CH   128                 // scan chunk per thread (== TT)
#define LB   64                  // scan warmup lookback (e^-64 ~ 1e-28)

// ---------------- scratch (static device globals; no allocation) -------------
// g_S layout: [tile][k][128]  (tile = n/128). Scan thread (k,c) writes one
// contiguous 256B block; GEMM CTA reads one contiguous 64KB tile block.
__device__ __nv_bfloat16 g_S[(size_t)Kdim * Ndim];
__device__ float  g_psum[Kdim * NTILES];
__device__ float  g_Mu0[Kdim];
__device__ double g_ll;

__global__ void k_zero() { g_ll = 0.0; }

// ---------------- scan: truncated exponential-kernel recursion + row partials
// S[k][n] = Beta[k]*H(n-1), H(i) = decay*(H(i-1)+obs[k][i]); decay <= e^-1 so a
// 64-step warmup reproduces H to ~1e-28. Also accumulates chunk sum for Mu0.
__global__ __launch_bounds__(256) void k_scan(const float* __restrict__ obs,
                                              const float* __restrict__ Beta) {
    int u  = blockIdx.x * blockDim.x + threadIdx.x;  // 256*512 threads
    int k  = u >> 9;                                  // row
    int c  = u & 511;                                 // chunk/tile index
    int n0 = c * CH;

    float beta  = Beta[k];
    float decay = __expf(-beta);
    const float*  orow  = obs + (size_t)k * Ndim;
    const float4* orow4 = (const float4*)orow;

    // ---- warmup: h over i in [n0-64, n0-2] (o[n0-1] handled as prev below)
    float h = 0.f;
    if (c > 0) {
        int j0 = (n0 - 64) >> 2;
        #pragma unroll
        for (int j = 0; j < 16; ++j) {
            float4 f = __ldg(orow4 + j0 + j);
            h = decay * (h + f.x);
            h = decay * (h + f.y);
            h = decay * (h + f.z);
            if (j < 15) h = decay * (h + f.w);  // skip i = n0-1
        }
    }

    float prev = (n0 > 0) ? __ldg(orow + n0 - 1) : 0.f;
    float sum = 0.f;

    union { __nv_bfloat16 b[8]; uint4 v; } buf;
    uint4* outp = (uint4*)(g_S + ((size_t)c * Kdim + k) * CH);
    const float4* src = orow4 + (n0 >> 2);

    #pragma unroll
    for (int q = 0; q < CH / 8; ++q) {
        float4 a = __ldg(src + 2 * q);
        float4 b4 = __ldg(src + 2 * q + 1);
        float v[8] = {a.x, a.y, a.z, a.w, b4.x, b4.y, b4.z, b4.w};
        #pragma unroll
        for (int r = 0; r < 8; ++r) {
            int n = n0 + q * 8 + r;
            float val = 0.f;
            if (n > 0) {
                h = decay * (h + prev);
                val = beta * h;
            }
            buf.b[r] = __float2bfloat16(val);
            prev = v[r];
            sum += v[r];
        }
        outp[q] = buf.v;
    }
    g_psum[k * NTILES + c] = sum;
}

// ---------------- Mu0 reduction (deterministic fixed-order tree) -------------
__global__ void k_mu0(void) {
    __shared__ float red[128];
    int k = blockIdx.x, t = threadIdx.x;
    const float* p = g_psum + k * NTILES;
    float s = p[t] + p[t + 128] + p[t + 256] + p[t + 384];
    red[t] = s;
    __syncthreads();
    for (int o = 64; o > 0; o >>= 1) {
        if (t < o) red[t] += red[t + o];
        __syncthreads();
    }
    if (t == 0) g_Mu0[k] = red[0] * (1.0f / Ndim) * 0.1f + 0.01f;
}

// ---------------- bf16 mma helper --------------------------------------------
__device__ __forceinline__ void mma16816(float* c, const unsigned* a, unsigned b0, unsigned b1) {
    asm volatile(
        "mma.sync.aligned.m16n8k16.row.col.f32.bf16.bf16.f32 "
        "{%0,%1,%2,%3}, {%4,%5,%6,%7}, {%8,%9}, {%0,%1,%2,%3};\n"
        : "+f"(c[0]), "+f"(c[1]), "+f"(c[2]), "+f"(c[3])
        : "r"(a[0]), "r"(a[1]), "r"(a[2]), "r"(a[3]), "r"(b0), "r"(b1));
}

// ---------------- fused GEMM (lam1 = softplus(Alpha @ S)) + epilogue ---------
__global__ __launch_bounds__(256, 1) void k_gemm(
    const float* __restrict__ obs,
    const float* __restrict__ Alpha,
    float* __restrict__ out)
{
    extern __shared__ __align__(16) char smem[];
    __nv_bfloat16* As   = (__nv_bfloat16*)smem;        // [256][KPAD] bf16
    __nv_bfloat16* Ss   = As + 256 * KPAD;             // [TT][KPAD] bf16 (B tile)
    float*         Sf   = (float*)Ss;                  // alias: [128][132] f32 bounce
    float2*        Sf2  = (float2*)Ss;
    float*         Mu0s = (float*)(Ss + TT * KPAD);    // [256]
    double*        red  = (double*)(Mu0s + 256);       // [8]

    const int tid  = threadIdx.x;
    const int wid  = tid >> 5, lane = tid & 31;
    const int wj   = wid & 3;          // 4 warps along j (64 rows each)
    const int wt   = wid >> 2;         // 2 warps along t (64 cols each)
    const int lg   = lane >> 2;
    const int lm   = lane & 3;

    // Stage Alpha -> bf16 smem (row-major [j][k])
    const float4* A4 = (const float4*)Alpha;
    for (int idx = tid; idx < Kdim * Kdim / 4; idx += 256) {
        int j = idx >> 6, c4 = idx & 63;
        float4 v = A4[idx];
        __nv_bfloat162* dst = (__nv_bfloat162*)(As + j * KPAD + c4 * 4);
        dst[0] = __floats2bfloat162_rn(v.x, v.y);
        dst[1] = __floats2bfloat162_rn(v.z, v.w);
    }
    Mu0s[tid] = g_Mu0[tid];

    float* lams0 = out + 1;
    float* lams1 = out + 1 + (size_t)Kdim * Ndim;

    double lsum = 0.0;

    for (int tile = blockIdx.x; tile < NTILES; tile += gridDim.x) {
        const int n0 = tile * TT;
        __syncthreads();   // WAR on Ss vs previous epilogue (and Alpha staging)

        // Stage S tile transposed to Ss[t][k]; global read fully coalesced
        {
            const uint4* srow = (const uint4*)(g_S + ((size_t)tile * Kdim + tid) * TT);
            #pragma unroll
            for (int q = 0; q < TT / 8; ++q) {
                uint4 v = srow[q];
                const __nv_bfloat16* bb = (const __nv_bfloat16*)&v;
                #pragma unroll
                for (int r = 0; r < 8; ++r)
                    Ss[(q * 8 + r) * KPAD + tid] = bb[r];
            }
        }
        __syncthreads();

        float acc[4][8][4];
        #pragma unroll
        for (int a = 0; a < 4; ++a)
            #pragma unroll
            for (int b = 0; b < 8; ++b)
                #pragma unroll
                for (int d = 0; d < 4; ++d) acc[a][b][d] = 0.f;

        #pragma unroll
        for (int ks = 0; ks < Kdim / 16; ++ks) {
            const int kk = ks * 16;
            unsigned afrag[4][4];
            #pragma unroll
            for (int mf = 0; mf < 4; ++mf) {
                int j = wj * 64 + mf * 16 + lg;
                const unsigned* r0 = (const unsigned*)(As + j * KPAD + kk) + lm;
                const unsigned* r1 = (const unsigned*)(As + (j + 8) * KPAD + kk) + lm;
                afrag[mf][0] = r0[0];
                afrag[mf][1] = r1[0];
                afrag[mf][2] = r0[4];
                afrag[mf][3] = r1[4];
            }
            #pragma unroll
            for (int nf = 0; nf < 8; ++nf) {
                int t = wt * 64 + nf * 8 + lg;
                const unsigned* rb = (const unsigned*)(Ss + t * KPAD + kk) + lm;
                unsigned b0 = rb[0], b1 = rb[4];
                #pragma unroll
                for (int mf = 0; mf < 4; ++mf)
                    mma16816(acc[mf][nf], afrag[mf], b0, b1);
            }
        }

        // ---- Epilogue in 2 j-slices, bounced through smem for coalescing ----
        #pragma unroll
        for (int s = 0; s < 2; ++s) {
            __syncthreads();   // mma reads of Ss done (s=0) / prev slice consumed
            if ((wj >> 1) == s) {
                const int jbase = (wj & 1) * 64;
                #pragma unroll
                for (int mf = 0; mf < 4; ++mf)
                    #pragma unroll
                    for (int half = 0; half < 2; ++half) {
                        const int jl = jbase + mf * 16 + lg + half * 8;
                        #pragma unroll
                        for (int nf = 0; nf < 8; ++nf) {
                            const int t = wt * 64 + nf * 8 + lm * 2;
                            Sf2[(jl * 132 + t) >> 1] =
                                make_float2(acc[mf][nf][half * 2], acc[mf][nf][half * 2 + 1]);
                        }
                    }
            }
            __syncthreads();

            float fsum = 0.f;
            #pragma unroll 4
            for (int rr = 0; rr < 16; ++rr) {
                const int jl = wid * 16 + rr;
                const int jg = s * 128 + jl;
                const float mu = Mu0s[jg];
                const size_t rowbase = (size_t)jg * Ndim + n0;
                #pragma unroll
                for (int c4 = 0; c4 < 4; ++c4) {
                    const int nl = c4 * 32 + lane;
                    float z = Sf[jl * 132 + nl];
                    // softplus(z) = z + log(1 + e^-z); z >= 0 here
                    float lam = z + __logf(1.f + __expf(-z));
                    if (n0 + nl == 0) lam = 0.f;     // reference: lams1[:,0] = 0
                    const size_t base = rowbase + nl;
                    lams1[base] = lam;
                    lams0[base] = mu;
                    float o = __ldg(obs + base);
                    fsum += o * __logf(mu + lam + 1e-5f) - mu - lam;
                }
            }
            lsum += (double)fsum;
        }
    }

    // Reduce loglik: warp shuffle -> smem -> one atomicAdd(double) per CTA
    #pragma unroll
    for (int o = 16; o > 0; o >>= 1)
        lsum += __shfl_down_sync(0xffffffffu, lsum, o);
    if (lane == 0) red[wid] = lsum;
    __syncthreads();
    if (tid == 0) {
        double s = 0.0;
        #pragma unroll
        for (int i = 0; i < 8; ++i) s += red[i];
        atomicAdd(&g_ll, s);
    }
}

__global__ void k_final(float* __restrict__ out) { out[0] = (float)g_ll; }

// ---------------- launch ------------------------------------------------------
extern "C" void kernel_launch(void* const* d_in, const int* in_sizes, int n_in,
                              void* d_out, int out_size) {
    const float* obs   = (const float*)d_in[0];
    const float* Beta  = (const float*)d_in[1];
    const float* Alpha = (const float*)d_in[2];
    float* out = (float*)d_out;

    k_zero<<<1, 1>>>();
    k_scan<<<(Kdim * NTILES) / 256, 256>>>(obs, Beta);
    k_mu0<<<Kdim, 128>>>();

    const int smem_bytes = 256 * KPAD * 2 + TT * KPAD * 2 + 256 * 4 + 8 * 8;
    cudaFuncSetAttribute(k_gemm, cudaFuncAttributeMaxDynamicSharedMemorySize, smem_bytes);
    int nsm = 148;
    cudaDeviceGetAttribute(&nsm, cudaDevAttrMultiProcessorCount, 0);
    k_gemm<<<nsm, 256, smem_bytes>>>(obs, Alpha, out);

    k_final<<<1, 1>>>(out);
}

// round 3
// speedup vs baseline: 2.6005x; 1.1396x over previous
#include <cuda_runtime.h>
#include <cuda_bf16.h>

#define Kdim 256
#define Ndim 65536
#define TT   128                 // time-tile width
#define NTILES (Ndim / TT)       // 512
#define KPAD 264                 // K + 8 pad -> conflict-free fragment LDS

// ---------------- scratch (static device globals; no allocation) -------------
// g_S layout: [tile][k][128] bf16, tile = n/128. Stores H (Beta folded into A).
__device__ __nv_bfloat16 g_S[(size_t)Kdim * Ndim];
__device__ float  g_psum[Kdim * NTILES];
__device__ float  g_Mu0[Kdim];
__device__ double g_ll;

__global__ void k_zero() { g_ll = 0.0; }

// ---------------- scan: truncated exponential-kernel recursion ---------------
// H(n) for row k: H(i) = decay*(H(i-1)+obs[k][i-1]); decay <= e^-1, so a
// 32-step warmup reproduces H to ~1e-14 (bf16 eps is 4e-3).
// Block = 128 threads = 128 chunks of one quarter-row, fully smem-staged so
// all global traffic is coalesced (the old per-lane-chunk version generated
// 32 L1 wavefronts per LDG/STG instruction).
__global__ __launch_bounds__(128) void k_scan(const float* __restrict__ obs,
                                              const float* __restrict__ Beta) {
    extern __shared__ __align__(16) char sm[];
    float* obs_s = (float*)sm;                       // 128 chunks x 132 floats
    uint4* out_s = (uint4*)(sm + 128 * 132 * 4);     // 128 chunks x 16 uint4 (swizzled)

    const int tid = threadIdx.x;
    const int k   = blockIdx.x >> 2;
    const int qtr = blockIdx.x & 3;
    const float4* orow4 = (const float4*)(obs + (size_t)k * Ndim) + qtr * 4096;

    // ---- stage 64KB of obs, coalesced, into chunk-padded smem
    #pragma unroll
    for (int i = 0; i < 32; ++i) {
        float4 v = __ldg(orow4 + i * 128 + tid);
        int c = i * 4 + (tid >> 5);
        int w = (tid & 31) * 4;
        *(float4*)&obs_s[c * 132 + w] = v;
    }
    __syncthreads();

    const float decay = __expf(-Beta[k]);

    // ---- warmup over obs[n0-32 .. n0-1]  (last value becomes `prev`)
    float h = 0.f, prev = 0.f;
    if (tid > 0) {
        const float* wsrc = &obs_s[(tid - 1) * 132 + 96];
        #pragma unroll
        for (int j = 0; j < 8; ++j) {
            float4 f = *(const float4*)(wsrc + j * 4);
            h = decay * (h + f.x);
            h = decay * (h + f.y);
            h = decay * (h + f.z);
            if (j < 7) h = decay * (h + f.w); else prev = f.w;
        }
    } else if (qtr > 0) {
        const float4* g = (const float4*)(obs + (size_t)k * Ndim + qtr * 16384 - 32);
        #pragma unroll
        for (int j = 0; j < 8; ++j) {
            float4 f = __ldg(g + j);
            h = decay * (h + f.x);
            h = decay * (h + f.y);
            h = decay * (h + f.z);
            if (j < 7) h = decay * (h + f.w); else prev = f.w;
        }
    }
    // qtr==0 && tid==0: h=0, prev=0 -> H(0)=0 exactly as reference requires.

    // ---- recurrence over this thread's 128-step chunk (from smem)
    float sum = 0.f;
    const float* src = &obs_s[tid * 132];
    #pragma unroll
    for (int q = 0; q < 16; ++q) {
        float4 a = *(const float4*)(src + q * 8);
        float4 b = *(const float4*)(src + q * 8 + 4);
        float v[8] = {a.x, a.y, a.z, a.w, b.x, b.y, b.z, b.w};
        __nv_bfloat162 p[4];
        #pragma unroll
        for (int r = 0; r < 8; r += 2) {
            h = decay * (h + prev); float h0 = h; prev = v[r];
            h = decay * (h + prev); float h1 = h; prev = v[r + 1];
            p[r >> 1] = __floats2bfloat162_rn(h0, h1);
            sum += v[r] + v[r + 1];
        }
        out_s[tid * 16 + (q ^ (tid & 15))] = *(uint4*)p;   // XOR-swizzled store
    }
    g_psum[k * NTILES + qtr * 128 + tid] = sum;
    __syncthreads();

    // ---- cooperative coalesced store of the bf16 tile blocks
    uint4* g4 = (uint4*)g_S;
    #pragma unroll
    for (int j = 0; j < 16; ++j) {
        int idx = j * 128 + tid;
        int gc = idx >> 4, qq = idx & 15;
        uint4 v = out_s[gc * 16 + (qq ^ (gc & 15))];
        int tile = qtr * 128 + gc;
        g4[((size_t)tile * Kdim + k) * 16 + qq] = v;
    }
}

// ---------------- Mu0 reduction (deterministic fixed-order tree) -------------
__global__ void k_mu0(void) {
    __shared__ float red[128];
    int k = blockIdx.x, t = threadIdx.x;
    const float* p = g_psum + k * NTILES;
    float s = p[t] + p[t + 128] + p[t + 256] + p[t + 384];
    red[t] = s;
    __syncthreads();
    for (int o = 64; o > 0; o >>= 1) {
        if (t < o) red[t] += red[t + o];
        __syncthreads();
    }
    if (t == 0) g_Mu0[k] = red[0] * (1.0f / Ndim) * 0.1f + 0.01f;
}

// ---------------- bf16 mma helper --------------------------------------------
__device__ __forceinline__ void mma16816(float* c, const unsigned* a, unsigned b0, unsigned b1) {
    asm volatile(
        "mma.sync.aligned.m16n8k16.row.col.f32.bf16.bf16.f32 "
        "{%0,%1,%2,%3}, {%4,%5,%6,%7}, {%8,%9}, {%0,%1,%2,%3};\n"
        : "+f"(c[0]), "+f"(c[1]), "+f"(c[2]), "+f"(c[3])
        : "r"(a[0]), "r"(a[1]), "r"(a[2]), "r"(a[3]), "r"(b0), "r"(b1));
}

// ---------------- fused GEMM (lam1 = softplus((Alpha*Beta) @ H)) + epilogue --
// 512 threads, 16 warps (4 j-warps x 4 t-warps). Persistent CTAs; Alpha*Beta
// staged in smem once per CTA.
__global__ __launch_bounds__(512, 1) void k_gemm(
    const float* __restrict__ obs,
    const float* __restrict__ Alpha,
    const float* __restrict__ Beta,
    float* __restrict__ out)
{
    extern __shared__ __align__(16) char smem[];
    __nv_bfloat16* As   = (__nv_bfloat16*)smem;        // [256][KPAD] bf16
    __nv_bfloat16* Ss   = As + 256 * KPAD;             // [TT][KPAD] bf16 (B tile)
    float*         Sf   = (float*)Ss;                  // alias: [128][132] f32 bounce
    float2*        Sf2  = (float2*)Ss;
    float*         Mu0s = (float*)(Ss + TT * KPAD);    // [256]
    double*        red  = (double*)(Mu0s + 256);       // [16]

    const int tid  = threadIdx.x;
    const int wid  = tid >> 5, lane = tid & 31;
    const int wj   = wid & 3;          // 4 warps along j (64 rows each)
    const int wt   = wid >> 2;         // 4 warps along t (32 cols each)
    const int lg   = lane >> 2;
    const int lm   = lane & 3;

    // Stage Alpha*Beta -> bf16 smem (row-major [j][k])
    const float4* A4 = (const float4*)Alpha;
    const float4* B4 = (const float4*)Beta;
    for (int idx = tid; idx < Kdim * Kdim / 4; idx += 512) {
        int j = idx >> 6, c4 = idx & 63;
        float4 v = A4[idx];
        float4 b = __ldg(B4 + c4);
        v.x *= b.x; v.y *= b.y; v.z *= b.z; v.w *= b.w;
        __nv_bfloat162* dst = (__nv_bfloat162*)(As + j * KPAD + c4 * 4);
        dst[0] = __floats2bfloat162_rn(v.x, v.y);
        dst[1] = __floats2bfloat162_rn(v.z, v.w);
    }
    if (tid < 256) Mu0s[tid] = g_Mu0[tid];

    float* lams0 = out + 1;
    float* lams1 = out + 1 + (size_t)Kdim * Ndim;

    double lsum = 0.0;

    for (int tile = blockIdx.x; tile < NTILES; tile += gridDim.x) {
        const int n0 = tile * TT;
        __syncthreads();   // WAR on Ss vs previous epilogue (and Alpha staging)

        // Stage S tile transposed to Ss[t][k]; global read fully coalesced.
        {
            const int row = tid & 255;
            const int hq  = tid >> 8;            // 2 thread-halves split q range
            const uint4* srow = (const uint4*)(g_S + ((size_t)tile * Kdim + row) * TT) + hq * 8;
            #pragma unroll
            for (int qi = 0; qi < 8; ++qi) {
                uint4 v = srow[qi];
                const __nv_bfloat16* bb = (const __nv_bfloat16*)&v;
                const int q = hq * 8 + qi;
                #pragma unroll
                for (int r = 0; r < 8; ++r)
                    Ss[(q * 8 + r) * KPAD + row] = bb[r];
            }
        }
        __syncthreads();

        float acc[4][4][4];
        #pragma unroll
        for (int a = 0; a < 4; ++a)
            #pragma unroll
            for (int b = 0; b < 4; ++b)
                #pragma unroll
                for (int d = 0; d < 4; ++d) acc[a][b][d] = 0.f;

        #pragma unroll
        for (int ks = 0; ks < Kdim / 16; ++ks) {
            const int kk = ks * 16;
            unsigned afrag[4][4];
            #pragma unroll
            for (int mf = 0; mf < 4; ++mf) {
                int j = wj * 64 + mf * 16 + lg;
                const unsigned* r0 = (const unsigned*)(As + j * KPAD + kk) + lm;
                const unsigned* r1 = (const unsigned*)(As + (j + 8) * KPAD + kk) + lm;
                afrag[mf][0] = r0[0];
                afrag[mf][1] = r1[0];
                afrag[mf][2] = r0[4];
                afrag[mf][3] = r1[4];
            }
            #pragma unroll
            for (int nf = 0; nf < 4; ++nf) {
                int t = wt * 32 + nf * 8 + lg;
                const unsigned* rb = (const unsigned*)(Ss + t * KPAD + kk) + lm;
                unsigned b0 = rb[0], b1 = rb[4];
                #pragma unroll
                for (int mf = 0; mf < 4; ++mf)
                    mma16816(acc[mf][nf], afrag[mf], b0, b1);
            }
        }

        // ---- Epilogue in 2 j-slices, bounced through smem for coalescing ----
        #pragma unroll
        for (int s = 0; s < 2; ++s) {
            __syncthreads();   // s=0: MMA reads of Ss done; s=1: prev slice consumed
            if ((wj >> 1) == s) {
                const int jbase = (wj & 1) * 64;
                #pragma unroll
                for (int mf = 0; mf < 4; ++mf)
                    #pragma unroll
                    for (int half = 0; half < 2; ++half) {
                        const int jl = jbase + mf * 16 + lg + half * 8;
                        #pragma unroll
                        for (int nf = 0; nf < 4; ++nf) {
                            const int t = wt * 32 + nf * 8 + lm * 2;
                            Sf2[(jl * 132 + t) >> 1] =
                                make_float2(acc[mf][nf][half * 2], acc[mf][nf][half * 2 + 1]);
                        }
                    }
            }
            __syncthreads();

            float fsum = 0.f;
            #pragma unroll
            for (int rr = 0; rr < 8; ++rr) {
                const int jl = wid * 8 + rr;
                const int jg = s * 128 + jl;
                const float mu = Mu0s[jg];
                const size_t rowbase = (size_t)jg * Ndim + n0;
                #pragma unroll
                for (int c4 = 0; c4 < 4; ++c4) {
                    const int nl = c4 * 32 + lane;
                    float z = Sf[jl * 132 + nl];
                    // softplus(z) = z + log(1 + e^-z); z >= 0 here
                    float lam = z + __logf(1.f + __expf(-z));
                    if (n0 + nl == 0) lam = 0.f;     // reference: lams1[:,0] = 0
                    const size_t base = rowbase + nl;
                    lams1[base] = lam;
                    lams0[base] = mu;
                    float o = __ldg(obs + base);
                    fsum += o * __logf(mu + lam + 1e-5f) - mu - lam;
                }
            }
            lsum += (double)fsum;
        }
    }

    // Reduce loglik: warp shuffle -> smem -> one atomicAdd(double) per CTA
    #pragma unroll
    for (int o = 16; o > 0; o >>= 1)
        lsum += __shfl_down_sync(0xffffffffu, lsum, o);
    if (lane == 0) red[wid] = lsum;
    __syncthreads();
    if (tid == 0) {
        double s = 0.0;
        #pragma unroll
        for (int i = 0; i < 16; ++i) s += red[i];
        atomicAdd(&g_ll, s);
    }
}

__global__ void k_final(float* __restrict__ out) { out[0] = (float)g_ll; }

// ---------------- launch ------------------------------------------------------
extern "C" void kernel_launch(void* const* d_in, const int* in_sizes, int n_in,
                              void* d_out, int out_size) {
    const float* obs   = (const float*)d_in[0];
    const float* Beta  = (const float*)d_in[1];
    const float* Alpha = (const float*)d_in[2];
    float* out = (float*)d_out;

    k_zero<<<1, 1>>>();

    const int scan_smem = 128 * 132 * 4 + 128 * 16 * 16;   // 100352 B
    cudaFuncSetAttribute(k_scan, cudaFuncAttributeMaxDynamicSharedMemorySize, scan_smem);
    k_scan<<<Kdim * 4, 128, scan_smem>>>(obs, Beta);

    k_mu0<<<Kdim, 128>>>();

    const int smem_bytes = 256 * KPAD * 2 + TT * KPAD * 2 + 256 * 4 + 16 * 8;
    cudaFuncSetAttribute(k_gemm, cudaFuncAttributeMaxDynamicSharedMemorySize, smem_bytes);
    int nsm = 148;
    cudaDeviceGetAttribute(&nsm, cudaDevAttrMultiProcessorCount, 0);
    k_gemm<<<nsm, 512, smem_bytes>>>(obs, Alpha, Beta, out);

    k_final<<<1, 1>>>(out);
}

// round 4
// speedup vs baseline: 2.6242x; 1.0091x over previous
#include <cuda_runtime.h>
#include <cuda_bf16.h>

#define Kdim 256
#define Ndim 65536
#define TT   64                  // GEMM time-tile width
#define NTILES (Ndim / TT)       // 1024
#define CHUNKS 512               // scan chunks per row (128 steps each)

// ---------------- scratch (static device globals; no allocation) -------------
// g_S layout: [tile64][k][64] bf16 (tile = n/64). Stores H (Beta folded into A).
__device__ __nv_bfloat16 g_S[(size_t)Kdim * Ndim];
__device__ float  g_psum[Kdim * CHUNKS];
__device__ float  g_Mu0[Kdim];
__device__ double g_ll;

// ---------------- scan: truncated exponential-kernel recursion ---------------
// H(n) for row k: H(i) = decay*(H(i-1)+obs[k][i-1]); decay <= e^-1, so a
// 32-step warmup reproduces H to ~1e-14 (bf16 eps is 4e-3).
__global__ __launch_bounds__(128) void k_scan(const float* __restrict__ obs,
                                              const float* __restrict__ Beta) {
    extern __shared__ __align__(16) char sm[];
    float* obs_s = (float*)sm;                       // 128 chunks x 132 floats
    uint4* out_s = (uint4*)(sm + 128 * 132 * 4);     // 128 chunks x 16 uint4 (swizzled)

    const int tid = threadIdx.x;
    const int k   = blockIdx.x >> 2;
    const int qtr = blockIdx.x & 3;
    if (blockIdx.x == 0 && tid == 0) g_ll = 0.0;     // fold k_zero here
    const float4* orow4 = (const float4*)(obs + (size_t)k * Ndim) + qtr * 4096;

    // ---- stage 64KB of obs, coalesced, into chunk-padded smem
    #pragma unroll
    for (int i = 0; i < 32; ++i) {
        float4 v = __ldg(orow4 + i * 128 + tid);
        int c = i * 4 + (tid >> 5);
        int w = (tid & 31) * 4;
        *(float4*)&obs_s[c * 132 + w] = v;
    }
    __syncthreads();

    const float decay = __expf(-Beta[k]);

    // ---- warmup over obs[n0-32 .. n0-1]  (last value becomes `prev`)
    float h = 0.f, prev = 0.f;
    if (tid > 0) {
        const float* wsrc = &obs_s[(tid - 1) * 132 + 96];
        #pragma unroll
        for (int j = 0; j < 8; ++j) {
            float4 f = *(const float4*)(wsrc + j * 4);
            h = decay * (h + f.x);
            h = decay * (h + f.y);
            h = decay * (h + f.z);
            if (j < 7) h = decay * (h + f.w); else prev = f.w;
        }
    } else if (qtr > 0) {
        const float4* g = (const float4*)(obs + (size_t)k * Ndim + qtr * 16384 - 32);
        #pragma unroll
        for (int j = 0; j < 8; ++j) {
            float4 f = __ldg(g + j);
            h = decay * (h + f.x);
            h = decay * (h + f.y);
            h = decay * (h + f.z);
            if (j < 7) h = decay * (h + f.w); else prev = f.w;
        }
    }
    // qtr==0 && tid==0: h=0, prev=0 -> H(0)=0 exactly as reference requires.

    // ---- recurrence over this thread's 128-step chunk (from smem)
    float sum = 0.f;
    const float* src = &obs_s[tid * 132];
    #pragma unroll
    for (int q = 0; q < 16; ++q) {
        float4 a = *(const float4*)(src + q * 8);
        float4 b = *(const float4*)(src + q * 8 + 4);
        float v[8] = {a.x, a.y, a.z, a.w, b.x, b.y, b.z, b.w};
        __nv_bfloat162 p[4];
        #pragma unroll
        for (int r = 0; r < 8; r += 2) {
            h = decay * (h + prev); float h0 = h; prev = v[r];
            h = decay * (h + prev); float h1 = h; prev = v[r + 1];
            p[r >> 1] = __floats2bfloat162_rn(h0, h1);
            sum += v[r] + v[r + 1];
        }
        out_s[tid * 16 + (q ^ (tid & 15))] = *(uint4*)p;   // XOR-swizzled store
    }
    g_psum[k * CHUNKS + qtr * 128 + tid] = sum;
    __syncthreads();

    // ---- cooperative coalesced store into [tile64][k][64] blocks
    uint4* g4 = (uint4*)g_S;
    #pragma unroll
    for (int j = 0; j < 16; ++j) {
        int idx = j * 128 + tid;
        int gc = idx >> 4, qq = idx & 15;
        uint4 v = out_s[gc * 16 + (qq ^ (gc & 15))];
        int tile = (qtr * 128 + gc) * 2 + (qq >> 3);
        g4[((size_t)tile * Kdim + k) * 8 + (qq & 7)] = v;
    }
}

// ---------------- Mu0 reduction (deterministic fixed-order tree) -------------
__global__ void k_mu0(void) {
    __shared__ float red[128];
    int k = blockIdx.x, t = threadIdx.x;
    const float* p = g_psum + k * CHUNKS;
    float s = p[t] + p[t + 128] + p[t + 256] + p[t + 384];
    red[t] = s;
    __syncthreads();
    for (int o = 64; o > 0; o >>= 1) {
        if (t < o) red[t] += red[t + o];
        __syncthreads();
    }
    if (t == 0) g_Mu0[k] = red[0] * (1.0f / Ndim) * 0.1f + 0.01f;
}

// ---------------- mma / ldmatrix helpers -------------------------------------
__device__ __forceinline__ void mma16816(float* c, const unsigned* a, unsigned b0, unsigned b1) {
    asm volatile(
        "mma.sync.aligned.m16n8k16.row.col.f32.bf16.bf16.f32 "
        "{%0,%1,%2,%3}, {%4,%5,%6,%7}, {%8,%9}, {%0,%1,%2,%3};\n"
        : "+f"(c[0]), "+f"(c[1]), "+f"(c[2]), "+f"(c[3])
        : "r"(a[0]), "r"(a[1]), "r"(a[2]), "r"(a[3]), "r"(b0), "r"(b1));
}
__device__ __forceinline__ void ldmx4(unsigned& r0, unsigned& r1, unsigned& r2, unsigned& r3,
                                      unsigned addr) {
    asm volatile("ldmatrix.sync.aligned.m8n8.x4.shared.b16 {%0,%1,%2,%3}, [%4];"
                 : "=r"(r0), "=r"(r1), "=r"(r2), "=r"(r3) : "r"(addr));
}
__device__ __forceinline__ void ldmx4t(unsigned& r0, unsigned& r1, unsigned& r2, unsigned& r3,
                                       unsigned addr) {
    asm volatile("ldmatrix.sync.aligned.m8n8.x4.trans.shared.b16 {%0,%1,%2,%3}, [%4];"
                 : "=r"(r0), "=r"(r1), "=r"(r2), "=r"(r3) : "r"(addr));
}

// smem byte offsets
#define SOFF_A   0
#define SOFF_S0  131072
#define SOFF_S1  163840
#define SOFF_MU  196608
#define SOFF_RED 197632
#define SMEM_TOT 197760

// ---------------- fused GEMM (lam1 = softplus((Alpha*Beta) @ H)) + epilogue --
// 512 threads, 16 warps (4 j-warps x 4 t-warps). Persistent CTAs; Alpha*Beta
// staged swizzled in smem once. S tiles double-buffered via cp.async; B frags
// via ldmatrix.trans (no smem transpose). Epilogue bounces through the
// just-consumed S buffer with XOR swizzle; all global traffic 128B-coalesced.
__global__ __launch_bounds__(512, 1) void k_gemm(
    const float* __restrict__ obs,
    const float* __restrict__ Alpha,
    const float* __restrict__ Beta,
    float* __restrict__ out)
{
    extern __shared__ __align__(16) char smem[];
    float*  Mu0s = (float*)(smem + SOFF_MU);
    double* red  = (double*)(smem + SOFF_RED);
    const unsigned smem_u32 = (unsigned)__cvta_generic_to_shared(smem);

    const int tid  = threadIdx.x;
    const int wid  = tid >> 5, lane = tid & 31;
    const int wj   = wid & 3;          // 4 warps along j (64 rows each)
    const int wt   = wid >> 2;         // 4 warps along t (16 cols each)
    const int lg   = lane >> 2;
    const int lm   = lane & 3;

    // ---- prefetch tile 0 into S buffer 0
    {
        int tile = blockIdx.x;
        const char* src = (const char*)g_S + (size_t)tile * (Kdim * TT * 2);
        #pragma unroll
        for (int i = 0; i < 4; ++i) {
            int idx = tid + i * 512;           // 16B segment id, 0..2047
            int k = idx >> 3, s = idx & 7;
            unsigned dst = smem_u32 + SOFF_S0 + k * 128 + ((s ^ (k & 7)) << 4);
            asm volatile("cp.async.cg.shared.global [%0], [%1], 16;"
                         :: "r"(dst), "l"(src + idx * 16));
        }
        asm volatile("cp.async.commit_group;");
    }

    // ---- stage Alpha*Beta -> swizzled bf16 smem [j][k] (row 512B, seg XOR)
    {
        const float4* A4 = (const float4*)Alpha;
        const float4* B4 = (const float4*)Beta;
        for (int idx = tid; idx < 8192; idx += 512) {   // 16B chunks
            int j = idx >> 5, s = idx & 31;             // s: 8-k segment
            float4 v0 = A4[j * 64 + s * 2];
            float4 v1 = A4[j * 64 + s * 2 + 1];
            float4 b0 = __ldg(B4 + s * 2);
            float4 b1 = __ldg(B4 + s * 2 + 1);
            __nv_bfloat162 pk[4];
            pk[0] = __floats2bfloat162_rn(v0.x * b0.x, v0.y * b0.y);
            pk[1] = __floats2bfloat162_rn(v0.z * b0.z, v0.w * b0.w);
            pk[2] = __floats2bfloat162_rn(v1.x * b1.x, v1.y * b1.y);
            pk[3] = __floats2bfloat162_rn(v1.z * b1.z, v1.w * b1.w);
            int phys = (s & 24) | ((s & 7) ^ (j & 7));
            *(uint4*)(smem + SOFF_A + j * 512 + phys * 16) = *(uint4*)pk;
        }
        if (tid < 256) Mu0s[tid] = g_Mu0[tid];
    }

    // ---- precompute ldmatrix lane addresses
    const int jsw  = lane & 7;
    const int subk = lane >> 4;                         // 0/1: second 8-column half
    unsigned ja[4];
    #pragma unroll
    for (int mf = 0; mf < 4; ++mf) {
        int jrow = wj * 64 + mf * 16 + (lane & 8) + (lane & 7);
        ja[mf] = smem_u32 + SOFF_A + jrow * 512;
    }
    const int koff  = (lane & 8) + (lane & 7);
    const int tseg  = wt * 2 + subk;
    const unsigned bphys = ((unsigned)(tseg ^ jsw)) << 4;
    unsigned bbase[2] = { smem_u32 + SOFF_S0 + koff * 128 + bphys,
                          smem_u32 + SOFF_S1 + koff * 128 + bphys };
    const int sboff[2] = { SOFF_S0, SOFF_S1 };

    float* lams0 = out + 1;
    float* lams1 = out + 1 + (size_t)Kdim * Ndim;

    double lsum = 0.0;
    int p = 0;

    for (int tile = blockIdx.x; tile < NTILES; tile += gridDim.x) {
        asm volatile("cp.async.wait_group 0;" ::: "memory");
        __syncthreads();                           // tile data ready in buf[p]

        // ---- MMA
        float acc[4][2][4];
        #pragma unroll
        for (int a = 0; a < 4; ++a)
            #pragma unroll
            for (int b = 0; b < 2; ++b)
                #pragma unroll
                for (int d = 0; d < 4; ++d) acc[a][b][d] = 0.f;

        const unsigned bb = bbase[p];
        #pragma unroll
        for (int ks = 0; ks < 16; ++ks) {
            unsigned b0, b1, b2, b3;
            ldmx4t(b0, b1, b2, b3, bb + ks * 2048);
            const int sA = 2 * ks + subk;
            const unsigned aoff = (unsigned)(((sA & 24) | ((sA & 7) ^ jsw)) << 4);
            #pragma unroll
            for (int mf = 0; mf < 4; ++mf) {
                unsigned a[4];
                ldmx4(a[0], a[1], a[2], a[3], ja[mf] + aoff);
                mma16816(acc[mf][0], a, b0, b1);
                mma16816(acc[mf][1], a, b2, b3);
            }
        }
        __syncthreads();                           // all warps done reading buf[p]

        // ---- prefetch next tile into buf[p^1] (overlaps epilogue)
        {
            int nxt = tile + gridDim.x;
            if (nxt < NTILES) {
                const char* src = (const char*)g_S + (size_t)nxt * (Kdim * TT * 2);
                #pragma unroll
                for (int i = 0; i < 4; ++i) {
                    int idx = tid + i * 512;
                    int k = idx >> 3, s = idx & 7;
                    unsigned dst = smem_u32 + sboff[p ^ 1] + k * 128 + ((s ^ (k & 7)) << 4);
                    asm volatile("cp.async.cg.shared.global [%0], [%1], 16;"
                                 :: "r"(dst), "l"(src + idx * 16));
                }
            }
            asm volatile("cp.async.commit_group;");
        }

        // ---- epilogue: 2 j-slices of 128, bounced through consumed buf[p]
        float*  Sf  = (float*)(smem + sboff[p]);   // [128 j][64 t], grp-XOR swizzled
        float2* Sf2 = (float2*)Sf;
        const int n0 = tile * TT;

        #pragma unroll
        for (int s = 0; s < 2; ++s) {
            if ((wj >> 1) == s) {
                #pragma unroll
                for (int mf = 0; mf < 4; ++mf)
                    #pragma unroll
                    for (int half = 0; half < 2; ++half) {
                        const int jl = (wj & 1) * 64 + mf * 16 + lg + half * 8;
                        #pragma unroll
                        for (int nf = 0; nf < 2; ++nf) {
                            const int grp = wt * 2 + nf;               // t/8
                            const int gsw = grp ^ (jl & 7);
                            Sf2[jl * 32 + gsw * 4 + lm] =
                                make_float2(acc[mf][nf][half * 2], acc[mf][nf][half * 2 + 1]);
                        }
                    }
            }
            __syncthreads();

            float fsum = 0.f;
            const int jl0 = wid >> 1;
            const int tof = (wid & 1) * 32 + lane;
            #pragma unroll 4
            for (int pass = 0; pass < 16; ++pass) {
                const int jl = jl0 + pass * 8;
                const int jg = s * 128 + jl;
                float z = Sf[jl * 64 + (((tof >> 3) ^ (jl & 7)) << 3) + (tof & 7)];
                // softplus(z) = z + log(1 + e^-z); z >= 0 here
                float lam = z + __logf(1.f + __expf(-z));
                const int n = n0 + tof;
                if (n == 0) lam = 0.f;             // reference: lams1[:,0] = 0
                const float mu = Mu0s[jg];
                const size_t base = (size_t)jg * Ndim + n;
                lams1[base] = lam;
                lams0[base] = mu;
                float o = __ldg(obs + base);
                fsum += o * __logf(mu + lam + 1e-5f) - mu - lam;
            }
            lsum += (double)fsum;
            __syncthreads();
        }
        p ^= 1;
    }
    asm volatile("cp.async.wait_group 0;" ::: "memory");   // drain tail prefetch

    // Reduce loglik: warp shuffle -> smem -> one atomicAdd(double) per CTA
    #pragma unroll
    for (int o = 16; o > 0; o >>= 1)
        lsum += __shfl_down_sync(0xffffffffu, lsum, o);
    if (lane == 0) red[wid] = lsum;
    __syncthreads();
    if (tid == 0) {
        double s = 0.0;
        #pragma unroll
        for (int i = 0; i < 16; ++i) s += red[i];
        atomicAdd(&g_ll, s);
    }
}

__global__ void k_final(float* __restrict__ out) { out[0] = (float)g_ll; }

// ---------------- launch ------------------------------------------------------
extern "C" void kernel_launch(void* const* d_in, const int* in_sizes, int n_in,
                              void* d_out, int out_size) {
    const float* obs   = (const float*)d_in[0];
    const float* Beta  = (const float*)d_in[1];
    const float* Alpha = (const float*)d_in[2];
    float* out = (float*)d_out;

    const int scan_smem = 128 * 132 * 4 + 128 * 16 * 16;   // 100352 B
    cudaFuncSetAttribute(k_scan, cudaFuncAttributeMaxDynamicSharedMemorySize, scan_smem);
    k_scan<<<Kdim * 4, 128, scan_smem>>>(obs, Beta);

    k_mu0<<<Kdim, 128>>>();

    cudaFuncSetAttribute(k_gemm, cudaFuncAttributeMaxDynamicSharedMemorySize, SMEM_TOT);
    int nsm = 148;
    cudaDeviceGetAttribute(&nsm, cudaDevAttrMultiProcessorCount, 0);
    k_gemm<<<nsm, 512, SMEM_TOT>>>(obs, Alpha, Beta, out);

    k_final<<<1, 1>>>(out);
}